// round 16
// baseline (speedup 1.0000x reference)
#include <cuda_runtime.h>
#include <cuda_fp16.h>
#include <cstdint>
#include <cstddef>

#define BATCH 2
#define DIM 128
#define CIN 64
#define COUT 64
#define HH 96
#define WW 96
#define HW (HH*WW)           // 9216
#define HEADS 8
#define CH 16
#define DEPTH 4
#define NIDX (BATCH*HH)      // 192 (b,y) slots for bn partials

// ---------------- scratch (device globals) ----------------
__device__ __align__(16) float g_t  [BATCH*DIM*HW];   // conv out (fp32, pre-BN)
__device__ __align__(16) float g_bn [BATCH*DIM*HW];   // bn+relu out (fp32 residual)
__device__ __align__(16) float g_qkv[BATCH*3*DIM*HW];
__device__ __align__(16) uint32_t g_hsp[BATCH*64*HW]; // half2 h
__device__ __align__(16) uint32_t g_qsp[BATCH*64*HW]; // half2 bn
__device__ __align__(16) uint32_t g_asp[BATCH*64*HW]; // half2 att
__device__ __align__(16) uint32_t g_xsp[BATCH*32*HW]; // half2 input x
__device__ float g_ps[DIM*NIDX];
__device__ float g_pq[DIM*NIDX];
// weights: exact fp16 split, SEPARATE hi/lo planes, layout [K/2][M]
#define NC (DEPTH*9*64*DIM)
#define NQ (DEPTH*64*3*DIM)
#define NF (DEPTH*64*DIM)
#define NI (32*DIM)
#define NO (64*COUT)
#define NTOT (NC+NQ+NF+NI+NO)
#define NSX (BATCH*32*HW)
__device__ uint32_t g_cwh[NC], g_cwl[NC];
__device__ uint32_t g_qwh[NQ], g_qwl[NQ];
__device__ uint32_t g_fwh[NF], g_fwl[NF];
__device__ uint32_t g_wih[NI], g_wil[NI];
__device__ uint32_t g_woh[NO], g_wol[NO];

__device__ __forceinline__ uint32_t h2(float a, float b)
{
    __half2 h = __floats2half2_rn(a, b);
    return *reinterpret_cast<uint32_t*>(&h);
}
__device__ __forceinline__ void splitw(float x0, float x1, uint32_t& hi, uint32_t& lo)
{
    __half h0 = __float2half_rn(x0);
    __half h1 = __float2half_rn(x1);
    float l0 = x0 - __half2float(h0);
    float l1 = x1 - __half2float(h1);
    __half2 hh = __halves2half2(h0, h1);
    __half2 ll = __floats2half2_rn(l0, l1);
    hi = *reinterpret_cast<uint32_t*>(&hh);
    lo = *reinterpret_cast<uint32_t*>(&ll);
}

__device__ __forceinline__ void mma_f16(float c[4],
    uint32_t a0, uint32_t a1, uint32_t a2, uint32_t a3, uint32_t b0, uint32_t b1)
{
    asm volatile(
        "mma.sync.aligned.m16n8k16.row.col.f32.f16.f16.f32 "
        "{%0,%1,%2,%3}, {%4,%5,%6,%7}, {%8,%9}, {%0,%1,%2,%3};"
        : "+f"(c[0]), "+f"(c[1]), "+f"(c[2]), "+f"(c[3])
        : "r"(a0), "r"(a1), "r"(a2), "r"(a3), "r"(b0), "r"(b1));
}

__device__ __forceinline__ uint32_t smem_u32(const void* p) {
    uint32_t a;
    asm("{ .reg .u64 t; cvta.to.shared.u64 t, %1; cvt.u32.u64 %0, t; }" : "=r"(a) : "l"(p));
    return a;
}
__device__ __forceinline__ void cpa4(uint32_t saddr, const void* g, bool v) {
    asm volatile("cp.async.ca.shared.global [%0], [%1], 4, %2;"
        :: "r"(saddr), "l"(g), "r"(v ? 4u : 0u));
}
#define CP_COMMIT() asm volatile("cp.async.commit_group;" ::: "memory")
#define CP_WAIT1()  asm volatile("cp.async.wait_group 1;" ::: "memory")

// ---------------- weight prep (hi/lo planes) + input split (fused) ----------------
__global__ void prep_all(const float* __restrict__ conv_w, const float* __restrict__ qkv_w,
                         const float* __restrict__ fc_w, const float* __restrict__ w_in,
                         const float* __restrict__ w_out, const float* __restrict__ x)
{
    int i = blockIdx.x*256 + threadIdx.x;
    float x0, x1; uint32_t *dh, *dl;
    if (i < NC) {
        int oc = i & 127; int r = i >> 7; int ic2 = r & 63; r >>= 6;
        int tap = r % 9, d = r / 9;
        size_t base = ((size_t)(d*DIM + oc)*DIM + 2*ic2)*9 + tap;
        x0 = conv_w[base]; x1 = conv_w[base + 9]; dh = &g_cwh[i]; dl = &g_cwl[i];
    } else if (i < NC+NQ) {
        int j = i - NC; int d = j / (64*384); int l = j % (64*384);
        int k2 = l / 384, m = l % 384;
        x0 = qkv_w[((size_t)d*384 + m)*DIM + 2*k2];
        x1 = qkv_w[((size_t)d*384 + m)*DIM + 2*k2 + 1];
        dh = &g_qwh[j]; dl = &g_qwl[j];
    } else if (i < NC+NQ+NF) {
        int j = i - NC - NQ; int d = j / (64*DIM); int l = j % (64*DIM);
        int k2 = l / DIM, m = l % DIM;
        x0 = fc_w[((size_t)d*DIM + m)*DIM + 2*k2];
        x1 = fc_w[((size_t)d*DIM + m)*DIM + 2*k2 + 1];
        dh = &g_fwh[j]; dl = &g_fwl[j];
    } else if (i < NC+NQ+NF+NI) {
        int j = i - NC - NQ - NF; int k2 = j / DIM, m = j % DIM;
        x0 = w_in[(size_t)m*CIN + 2*k2]; x1 = w_in[(size_t)m*CIN + 2*k2 + 1];
        dh = &g_wih[j]; dl = &g_wil[j];
    } else if (i < NTOT) {
        int j = i - NC - NQ - NF - NI; int k2 = j / COUT, m = j % COUT;
        x0 = w_out[(size_t)m*DIM + 2*k2]; x1 = w_out[(size_t)m*DIM + 2*k2 + 1];
        dh = &g_woh[j]; dl = &g_wol[j];
    } else if (i < NTOT + NSX) {
        int j = i - NTOT;
        int p = j % HW; int r = j / HW; int k2 = r & 31; int b = r >> 5;
        float a0 = x[((size_t)b*CIN + 2*k2)*HW + p];
        float a1 = x[((size_t)b*CIN + 2*k2 + 1)*HW + p];
        g_xsp[(size_t)b*32*HW + (size_t)k2*HW + p] = h2(a0, a1);
        return;
    } else return;
    uint32_t hi, lo; splitw(x0, x1, hi, lo);
    *dh = hi; *dl = lo;
}

// ---------------- fp16x2 GEMM (2-stage cp.async, K=32 chunks, 64m x 128n) ----------------
__global__ void gemm_f16(const uint32_t* __restrict__ Wh, const uint32_t* __restrict__ Wl,
                         const uint32_t* __restrict__ Bin,
                         const float* __restrict__ bias, const float* __restrict__ res,
                         void* __restrict__ Out, int osplit, int Mtot, int K)
{
    const int b  = blockIdx.z;
    const int m0 = blockIdx.y * 64, n0 = blockIdx.x * 128;

    __shared__ uint32_t As[2][2][16][72];
    __shared__ uint32_t Bs[2][16][136];

    const int tid  = threadIdx.x;
    const int warp = tid >> 5, lane = tid & 31;
    const int wm = warp >> 2, wn = warp & 3;
    const int g = lane >> 2, t = lane & 3;
    const int tt0 = tid >> 6, mcol = tid & 63;

    const uint32_t sA = smem_u32(As), sB = smem_u32(Bs);
    const uint32_t* Bsp = Bin + (size_t)b*(K/2)*HW;
    const int nk = K/32;
    float acc[2][4][4] = {};

#define G_ISSUE(c) do { \
        int s_ = (c) & 1; \
        _Pragma("unroll") \
        for (int r_ = 0; r_ < 4; r_++) { \
            int row_ = tt0 + r_*4; \
            cpa4(sA + (((s_*2+0)*16 + row_)*72 + mcol)*4, \
                 &Wh[(size_t)((c)*16 + row_)*Mtot + m0 + mcol], true); \
            cpa4(sA + (((s_*2+1)*16 + row_)*72 + mcol)*4, \
                 &Wl[(size_t)((c)*16 + row_)*Mtot + m0 + mcol], true); \
        } \
        _Pragma("unroll") \
        for (int j_ = 0; j_ < 8; j_++) { \
            int i_ = tid + j_*256; int tt_ = i_ >> 7; int n_ = i_ & 127; \
            cpa4(sB + ((s_*16 + tt_)*136 + n_)*4, \
                 &Bsp[(size_t)((c)*16 + tt_)*HW + n0 + n_], true); \
        } \
    } while(0)

    G_ISSUE(0); CP_COMMIT();
    if (nk > 1) G_ISSUE(1);
    CP_COMMIT();
    for (int c = 0; c < nk; c++) {
        const int cur = c & 1;
        CP_WAIT1();
        __syncthreads();

        #pragma unroll
        for (int sub = 0; sub < 2; sub++) {
            const int ro = sub*8;
            uint32_t ah[2][4], al[2][4];
            #pragma unroll
            for (int mt = 0; mt < 2; mt++) {
                int mrow = wm*32 + mt*16 + g;
                ah[mt][0] = As[cur][0][ro+t  ][mrow]; ah[mt][1] = As[cur][0][ro+t  ][mrow+8];
                ah[mt][2] = As[cur][0][ro+t+4][mrow]; ah[mt][3] = As[cur][0][ro+t+4][mrow+8];
                al[mt][0] = As[cur][1][ro+t  ][mrow]; al[mt][1] = As[cur][1][ro+t  ][mrow+8];
                al[mt][2] = As[cur][1][ro+t+4][mrow]; al[mt][3] = As[cur][1][ro+t+4][mrow+8];
            }
            #pragma unroll
            for (int nt = 0; nt < 4; nt++) {
                int col = wn*32 + nt*8 + g;
                uint32_t b0 = Bs[cur][ro+t][col], b1 = Bs[cur][ro+t+4][col];
                #pragma unroll
                for (int mt = 0; mt < 2; mt++) {
                    mma_f16(acc[mt][nt], ah[mt][0], ah[mt][1], ah[mt][2], ah[mt][3], b0, b1);
                    mma_f16(acc[mt][nt], al[mt][0], al[mt][1], al[mt][2], al[mt][3], b0, b1);
                }
            }
        }
        __syncthreads();
        if (c + 2 < nk) G_ISSUE(c + 2);
        CP_COMMIT();
    }
#undef G_ISSUE

    const float* Rb = res ? res + (size_t)b*Mtot*HW : nullptr;

    #pragma unroll
    for (int mt = 0; mt < 2; mt++) {
        const int row0 = m0 + wm*32 + mt*16 + g;
        const float b0v = bias ? bias[row0]     : 0.f;
        const float b1v = bias ? bias[row0 + 8] : 0.f;
        #pragma unroll
        for (int nt = 0; nt < 4; nt++) {
            int col = n0 + wn*32 + nt*8 + 2*t;
            float v00 = acc[mt][nt][0] + b0v, v01 = acc[mt][nt][1] + b0v;
            float v10 = acc[mt][nt][2] + b1v, v11 = acc[mt][nt][3] + b1v;
            if (Rb) {
                float2 r0 = *(const float2*)&Rb[(size_t)row0*HW + col];
                float2 r1 = *(const float2*)&Rb[(size_t)(row0+8)*HW + col];
                v00 += r0.x; v01 += r0.y; v10 += r1.x; v11 += r1.y;
            }
            if (!osplit) {
                float* Yb = (float*)Out + (size_t)b*Mtot*HW;
                *(float2*)&Yb[(size_t)row0*HW + col]     = make_float2(v00, v01);
                *(float2*)&Yb[(size_t)(row0+8)*HW + col] = make_float2(v10, v11);
            } else {
                float p00 = __shfl_xor_sync(0xffffffffu, v00, 4);
                float p01 = __shfl_xor_sync(0xffffffffu, v01, 4);
                float p10 = __shfl_xor_sync(0xffffffffu, v10, 4);
                float p11 = __shfl_xor_sync(0xffffffffu, v11, 4);
                if (!(g & 1)) {
                    uint32_t* Osp = (uint32_t*)Out + (size_t)b*64*HW;
                    int c2 = row0 >> 1;
                    *(uint2*)&Osp[(size_t)c2*HW + col]     = make_uint2(h2(v00,p00), h2(v01,p01));
                    *(uint2*)&Osp[(size_t)(c2+4)*HW + col] = make_uint2(h2(v10,p10), h2(v11,p11));
                }
            }
        }
    }
}

// ---------------- dilated 3x3 conv (fp16x2, 3-stage cp.async, K=32, 512 thr, 64m x 96n) --
// 16 warps as 4m x 4n; warp tile 16m x 24n.
__global__ void conv3x3_f16(const uint32_t* __restrict__ Bsp,
                            const uint32_t* __restrict__ CWh, const uint32_t* __restrict__ CWl,
                            const float* __restrict__ bias, float* __restrict__ Y, int d)
{
    const int m0 = blockIdx.x * 64;
    const int y  = blockIdx.y;
    const int b  = blockIdx.z;
    const uint32_t* Xb = Bsp + (size_t)b*64*HW;

    __shared__ uint32_t As[3][2][16][72];   // 27.0 KB
    __shared__ uint32_t Bs[3][16][104];     // 19.5 KB (aliased for bn staging after loop)

    const int tid  = threadIdx.x;
    const int warp = tid >> 5, lane = tid & 31;
    const int wm = warp >> 2, wn = warp & 3;
    const int g = lane >> 2, t = lane & 3;
    const int tt0 = tid >> 6, mcol = tid & 63;   // tt0 in 0..7

    const uint32_t sA = smem_u32(As), sB = smem_u32(Bs);

    int tidx[9], txs[9], roff[9], nv = 0;
    #pragma unroll
    for (int tap = 0; tap < 9; tap++) {
        int dy = tap/3 - 1, dx = tap%3 - 1;
        int yy = y + dy*d;
        if (yy >= 0 && yy < HH) {
            tidx[nv] = tap; txs[nv] = dx*d; roff[nv] = yy*WW; nv++;
        }
    }
    const int nchunks = nv * 4;             // K=32 per chunk

    float acc[3][4] = {};

#define C_ISSUE(cc) do { \
        int tv_ = (cc) >> 2, kc2_ = (cc) & 3; int icb_ = kc2_*16; int s_ = (cc) % 3; \
        const uint32_t* Wh_ = CWh + (size_t)tidx[tv_]*64*DIM; \
        const uint32_t* Wl_ = CWl + (size_t)tidx[tv_]*64*DIM; \
        _Pragma("unroll") \
        for (int r_ = 0; r_ < 2; r_++) { \
            int row_ = tt0 + r_*8; \
            cpa4(sA + (((s_*2+0)*16 + row_)*72 + mcol)*4, \
                 &Wh_[(size_t)(icb_ + row_)*DIM + m0 + mcol], true); \
            cpa4(sA + (((s_*2+1)*16 + row_)*72 + mcol)*4, \
                 &Wl_[(size_t)(icb_ + row_)*DIM + m0 + mcol], true); \
        } \
        const uint32_t* Xr_ = Xb + roff[tv_]; int sh_ = txs[tv_]; \
        _Pragma("unroll") \
        for (int j_ = 0; j_ < 3; j_++) { \
            int i_ = tid + j_*512; int tt_ = i_ / 96; int n_ = i_ - 96*tt_; \
            int xx_ = n_ + sh_; \
            bool v_ = (xx_ >= 0 && xx_ < WW); \
            int xc_ = v_ ? xx_ : 0; \
            cpa4(sB + ((s_*16 + tt_)*104 + n_)*4, \
                 &Xr_[(size_t)(icb_ + tt_)*HW + xc_], v_); \
        } \
    } while(0)

    C_ISSUE(0); CP_COMMIT();
    C_ISSUE(1); CP_COMMIT();
    for (int cc = 0; cc < nchunks; cc++) {
        const int cur = cc % 3;
        CP_WAIT1();
        __syncthreads();

        const int mrow = wm*16 + g;
        #pragma unroll
        for (int sub = 0; sub < 2; sub++) {
            const int ro = sub*8;
            uint32_t ah0 = As[cur][0][ro+t  ][mrow], ah1 = As[cur][0][ro+t  ][mrow+8];
            uint32_t ah2 = As[cur][0][ro+t+4][mrow], ah3 = As[cur][0][ro+t+4][mrow+8];
            uint32_t al0 = As[cur][1][ro+t  ][mrow], al1 = As[cur][1][ro+t  ][mrow+8];
            uint32_t al2 = As[cur][1][ro+t+4][mrow], al3 = As[cur][1][ro+t+4][mrow+8];
            #pragma unroll
            for (int nt = 0; nt < 3; nt++) {
                int col = wn*24 + nt*8 + g;
                uint32_t b0 = Bs[cur][ro+t][col], b1 = Bs[cur][ro+t+4][col];
                mma_f16(acc[nt], ah0, ah1, ah2, ah3, b0, b1);
                mma_f16(acc[nt], al0, al1, al2, al3, b0, b1);
            }
        }
        if (cc + 2 < nchunks) C_ISSUE(cc + 2);
        CP_COMMIT();
    }
#undef C_ISSUE

    float* Yb = Y + (size_t)b*DIM*HW + (size_t)y*WW;
    const int row0 = m0 + wm*16 + g;
    const float b0v = bias[row0], b1v = bias[row0 + 8];
    float s0 = 0.f, q0 = 0.f, s1 = 0.f, q1 = 0.f;
    #pragma unroll
    for (int nt = 0; nt < 3; nt++) {
        int col = wn*24 + nt*8 + 2*t;
        float v00 = acc[nt][0] + b0v, v01 = acc[nt][1] + b0v;
        float v10 = acc[nt][2] + b1v, v11 = acc[nt][3] + b1v;
        *(float2*)&Yb[(size_t)row0*HW + col]     = make_float2(v00, v01);
        *(float2*)&Yb[(size_t)(row0+8)*HW + col] = make_float2(v10, v11);
        s0 += v00 + v01; q0 += v00*v00 + v01*v01;
        s1 += v10 + v11; q1 += v10*v10 + v11*v11;
    }
    #pragma unroll
    for (int o = 1; o <= 2; o <<= 1) {
        s0 += __shfl_xor_sync(0xffffffffu, s0, o);
        q0 += __shfl_xor_sync(0xffffffffu, q0, o);
        s1 += __shfl_xor_sync(0xffffffffu, s1, o);
        q1 += __shfl_xor_sync(0xffffffffu, q1, o);
    }
    // bn partial staging aliased onto Bs (dead after main loop)
    // layout: S[wn][64] at [0..255], Q[wn][64] at [256..511]
    float* sSQ = (float*)Bs;
    __syncthreads();
    if (t == 0) {
        int lr = wm*16 + g;
        sSQ[wn*64 + lr]           = s0;  sSQ[256 + wn*64 + lr]        = q0;
        sSQ[wn*64 + lr + 8]       = s1;  sSQ[256 + wn*64 + lr + 8]    = q1;
    }
    __syncthreads();
    if (tid < 64) {
        int idx = b*HH + y;
        g_ps[(size_t)(m0+tid)*NIDX + idx] =
            sSQ[tid] + sSQ[64 + tid] + sSQ[128 + tid] + sSQ[192 + tid];
        g_pq[(size_t)(m0+tid)*NIDX + idx] =
            sSQ[256 + tid] + sSQ[320 + tid] + sSQ[384 + tid] + sSQ[448 + tid];
    }
}

// ---------------- bn apply + relu (inline stats) ----------------
__global__ void bn_apply_relu(const float* __restrict__ X, const float* __restrict__ gam,
                              const float* __restrict__ beta, float* __restrict__ Yf,
                              uint32_t* __restrict__ Ysp)
{
    const int b = blockIdx.y;
    int i = blockIdx.x*256 + threadIdx.x;
    int c2 = i / (HW/4);
    int p  = (i - c2*(HW/4)) * 4;
    int c0 = 2*c2, c1 = 2*c2 + 1;

    __shared__ float st[4];
    __shared__ float rs[4][8];
    {
        float s0=0.f, q0=0.f, s1=0.f, q1=0.f;
        int tt = threadIdx.x;
        if (tt < NIDX) {
            s0 = g_ps[(size_t)c0*NIDX + tt]; q0 = g_pq[(size_t)c0*NIDX + tt];
            s1 = g_ps[(size_t)c1*NIDX + tt]; q1 = g_pq[(size_t)c1*NIDX + tt];
        }
        #pragma unroll
        for (int o = 16; o > 0; o >>= 1) {
            s0 += __shfl_xor_sync(0xffffffffu, s0, o);
            q0 += __shfl_xor_sync(0xffffffffu, q0, o);
            s1 += __shfl_xor_sync(0xffffffffu, s1, o);
            q1 += __shfl_xor_sync(0xffffffffu, q1, o);
        }
        int w = threadIdx.x >> 5;
        if ((threadIdx.x & 31) == 0) {
            rs[0][w] = s0; rs[1][w] = q0; rs[2][w] = s1; rs[3][w] = q1;
        }
        __syncthreads();
        if (threadIdx.x == 0) {
            float S0=0,Q0=0,S1=0,Q1=0;
            #pragma unroll
            for (int k = 0; k < 8; k++) { S0+=rs[0][k]; Q0+=rs[1][k]; S1+=rs[2][k]; Q1+=rs[3][k]; }
            const float invN = 1.f / (BATCH*HW);
            float mm0 = S0*invN, mm1 = S1*invN;
            st[0] = mm0; st[1] = rsqrtf(Q0*invN - mm0*mm0 + 1e-5f);
            st[2] = mm1; st[3] = rsqrtf(Q1*invN - mm1*mm1 + 1e-5f);
        }
        __syncthreads();
    }
    float m0 = st[0], r0 = st[1], m1 = st[2], r1 = st[3];
    float ga0 = gam[c0], be0 = beta[c0], ga1 = gam[c1], be1 = beta[c1];

    const float* Xb = X + (size_t)b*DIM*HW;
    float* Yb = Yf + (size_t)b*DIM*HW;
    uint32_t* Sb = Ysp + (size_t)b*64*HW;

    float4 a = *(const float4*)&Xb[(size_t)c0*HW + p];
    float4 c = *(const float4*)&Xb[(size_t)c1*HW + p];
    float y0x = fmaxf((a.x-m0)*r0*ga0+be0, 0.f), y0y = fmaxf((a.y-m0)*r0*ga0+be0, 0.f);
    float y0z = fmaxf((a.z-m0)*r0*ga0+be0, 0.f), y0w = fmaxf((a.w-m0)*r0*ga0+be0, 0.f);
    float y1x = fmaxf((c.x-m1)*r1*ga1+be1, 0.f), y1y = fmaxf((c.y-m1)*r1*ga1+be1, 0.f);
    float y1z = fmaxf((c.z-m1)*r1*ga1+be1, 0.f), y1w = fmaxf((c.w-m1)*r1*ga1+be1, 0.f);

    *(float4*)&Yb[(size_t)c0*HW + p] = make_float4(y0x, y0y, y0z, y0w);
    *(float4*)&Yb[(size_t)c1*HW + p] = make_float4(y1x, y1y, y1z, y1w);

    *(uint4*)&Sb[(size_t)c2*HW + p] =
        make_uint4(h2(y0x, y1x), h2(y0y, y1y), h2(y0z, y1z), h2(y0w, y1w));
}

// ---------------- local channel self-attention (half2 epilogue) ----------------
__global__ void attn_core(const float* __restrict__ QKV, uint32_t* __restrict__ OUT)
{
    const int b = blockIdx.z, h = blockIdx.y;
    const int p0 = blockIdx.x * 32;
    const int y  = p0 / WW, x0 = p0 % WW;
    const float* Qb = QKV + ((size_t)b*3*DIM + h*CH)*HW;
    const float* Kb = Qb + (size_t)DIM*HW;
    const float* Vb = Qb + (size_t)2*DIM*HW;

    __shared__ float qs[CH][3][34];
    __shared__ float ks[CH][3][34];
    __shared__ float vs[CH][3][34];
    __shared__ float sato[CH][33];

    const int tid = threadIdx.y*32 + threadIdx.x;
    for (int i = tid; i < CH*3*34; i += 512) {
        int xi = i % 34; int rr = i / 34; int yi = rr % 3; int c = rr / 3;
        int yy = y + yi - 1, xx = x0 + xi - 1;
        bool ok = (yy >= 0 && yy < HH && xx >= 0 && xx < WW);
        int o = c*HW + yy*WW + xx;
        qs[c][yi][xi] = ok ? Qb[o] : 0.f;
        ks[c][yi][xi] = ok ? Kb[o] : 0.f;
        vs[c][yi][xi] = ok ? Vb[o] : 0.f;
    }
    __syncthreads();

    const int nn = threadIdx.y, lx = threadIdx.x;
    float qr[9];
    #pragma unroll
    for (int t = 0; t < 9; t++) qr[t] = qs[nn][t/3][lx + t%3] * 0.25f;

    float dots[CH], vsum[CH];
    #pragma unroll
    for (int m = 0; m < CH; m++) {
        float dv = 0.f, sv = 0.f;
        #pragma unroll
        for (int t = 0; t < 9; t++) {
            dv += qr[t] * ks[m][t/3][lx + t%3];
            sv += vs[m][t/3][lx + t%3];
        }
        dots[m] = dv; vsum[m] = sv;
    }
    float mx = dots[0];
    #pragma unroll
    for (int m = 1; m < CH; m++) mx = fmaxf(mx, dots[m]);
    float s = 0.f;
    #pragma unroll
    for (int m = 0; m < CH; m++) { dots[m] = __expf(dots[m]-mx); s += dots[m]; }
    float o = 0.f;
    #pragma unroll
    for (int m = 0; m < CH; m++) o += dots[m]*vsum[m];
    sato[nn][lx] = o / s;
    __syncthreads();

    if (nn < 8) {
        float v0 = sato[2*nn][lx], v1 = sato[2*nn+1][lx];
        OUT[(size_t)b*64*HW + (size_t)(h*8 + nn)*HW + p0 + lx] = h2(v0, v1);
    }
}

// ---------------- host orchestration ----------------
extern "C" void kernel_launch(void* const* d_in, const int* in_sizes, int n_in,
                              void* d_out, int out_size)
{
    const float* x      = (const float*)d_in[0];
    const float* w_in   = (const float*)d_in[1];
    const float* b_in   = (const float*)d_in[2];
    const float* conv_w = (const float*)d_in[3];
    const float* conv_b = (const float*)d_in[4];
    const float* bn_g   = (const float*)d_in[5];
    const float* bn_b   = (const float*)d_in[6];
    const float* qkv_w  = (const float*)d_in[7];
    const float* fc_w   = (const float*)d_in[8];
    const float* fc_b   = (const float*)d_in[9];
    const float* w_out  = (const float*)d_in[10];
    const float* b_out  = (const float*)d_in[11];
    float* out = (float*)d_out;

    float *p_t, *p_bn, *p_qkv;
    uint32_t *p_hsp, *p_qsp, *p_asp, *p_xsp;
    uint32_t *p_cwh, *p_cwl, *p_qwh, *p_qwl, *p_fwh, *p_fwl, *p_wih, *p_wil, *p_woh, *p_wol;
    cudaGetSymbolAddress((void**)&p_t,   g_t);
    cudaGetSymbolAddress((void**)&p_bn,  g_bn);
    cudaGetSymbolAddress((void**)&p_qkv, g_qkv);
    cudaGetSymbolAddress((void**)&p_hsp, g_hsp);
    cudaGetSymbolAddress((void**)&p_qsp, g_qsp);
    cudaGetSymbolAddress((void**)&p_asp, g_asp);
    cudaGetSymbolAddress((void**)&p_xsp, g_xsp);
    cudaGetSymbolAddress((void**)&p_cwh, g_cwh);
    cudaGetSymbolAddress((void**)&p_cwl, g_cwl);
    cudaGetSymbolAddress((void**)&p_qwh, g_qwh);
    cudaGetSymbolAddress((void**)&p_qwl, g_qwl);
    cudaGetSymbolAddress((void**)&p_fwh, g_fwh);
    cudaGetSymbolAddress((void**)&p_fwl, g_fwl);
    cudaGetSymbolAddress((void**)&p_wih, g_wih);
    cudaGetSymbolAddress((void**)&p_wil, g_wil);
    cudaGetSymbolAddress((void**)&p_woh, g_woh);
    cudaGetSymbolAddress((void**)&p_wol, g_wol);

    prep_all<<<(NTOT + NSX + 255)/256, 256>>>(conv_w, qkv_w, fc_w, w_in, w_out, x);

    // input projection 64 -> 128, half2 output into g_hsp
    {
        dim3 g(HW/128, DIM/64, BATCH);
        gemm_f16<<<g, 256>>>(p_wih, p_wil, p_xsp, b_in, nullptr, p_hsp, 1, DIM, CIN);
    }

    for (int i = 0; i < DEPTH; i++) {
        const int d = 1 << i;
        {   // dilated conv (K=32 chunks, 3-stage, 512 threads / 16 warps)
            dim3 g(2, HH, BATCH);
            conv3x3_f16<<<g, 512>>>(p_hsp, p_cwh + (size_t)i*9*64*DIM,
                                    p_cwl + (size_t)i*9*64*DIM, conv_b + i*DIM, p_t, d);
        }
        {   // bn + relu -> fp32 residual + half2 qkv input
            dim3 g((64*HW/4)/256, BATCH);
            bn_apply_relu<<<g, 256>>>(p_t, bn_g + i*DIM, bn_b + i*DIM, p_bn, p_qsp);
        }
        {   // qkv: 128 -> 384
            dim3 g(HW/128, (3*DIM)/64, BATCH);
            gemm_f16<<<g, 256>>>(p_qwh + (size_t)i*64*3*DIM, p_qwl + (size_t)i*64*3*DIM,
                                 p_qsp, nullptr, nullptr, p_qkv, 0, 3*DIM, DIM);
        }
        {   // attention -> half2 att
            dim3 g(HW/32, HEADS, BATCH);
            dim3 blk(32, CH);
            attn_core<<<g, blk>>>(p_qkv, p_asp);
        }
        {   // fc + bias + residual -> half2 h
            dim3 g(HW/128, DIM/64, BATCH);
            gemm_f16<<<g, 256>>>(p_fwh + (size_t)i*64*DIM, p_fwl + (size_t)i*64*DIM,
                                 p_asp, fc_b + i*DIM, p_bn, p_hsp, 1, DIM, DIM);
        }
    }

    // output projection 128 -> 64
    {
        dim3 g(HW/128, COUT/64, BATCH);
        gemm_f16<<<g, 256>>>(p_woh, p_wol, p_hsp, b_out, nullptr, out, 0, COUT, DIM);
    }
}

// round 17
// speedup vs baseline: 1.1375x; 1.1375x over previous
#include <cuda_runtime.h>
#include <cuda_fp16.h>
#include <cstdint>
#include <cstddef>

#define BATCH 2
#define DIM 128
#define CIN 64
#define COUT 64
#define HH 96
#define WW 96
#define HW (HH*WW)           // 9216
#define HEADS 8
#define CH 16
#define DEPTH 4
#define NIDX (BATCH*HH)      // 192 (b,y) slots for bn partials

// ---------------- scratch (device globals) ----------------
__device__ __align__(16) float g_t  [BATCH*DIM*HW];   // conv out (fp32, pre-BN)
__device__ __align__(16) float g_bn [BATCH*DIM*HW];   // bn+relu out (fp32 residual)
__device__ __align__(16) float g_qkv[BATCH*3*DIM*HW];
__device__ __align__(16) uint32_t g_hsp[BATCH*64*HW]; // half2 h
__device__ __align__(16) uint32_t g_qsp[BATCH*64*HW]; // half2 bn
__device__ __align__(16) uint32_t g_asp[BATCH*64*HW]; // half2 att
__device__ __align__(16) uint32_t g_xsp[BATCH*32*HW]; // half2 input x
__device__ float g_ps[DIM*NIDX];
__device__ float g_pq[DIM*NIDX];
// weights: exact fp16 split, SEPARATE hi/lo planes, layout [K/2][M]
#define NC (DEPTH*9*64*DIM)
#define NQ (DEPTH*64*3*DIM)
#define NF (DEPTH*64*DIM)
#define NI (32*DIM)
#define NO (64*COUT)
#define NTOT (NC+NQ+NF+NI+NO)
#define NSX (BATCH*32*HW)
__device__ __align__(16) uint32_t g_cwh[NC], g_cwl[NC];
__device__ __align__(16) uint32_t g_qwh[NQ], g_qwl[NQ];
__device__ __align__(16) uint32_t g_fwh[NF], g_fwl[NF];
__device__ __align__(16) uint32_t g_wih[NI], g_wil[NI];
__device__ __align__(16) uint32_t g_woh[NO], g_wol[NO];

__device__ __forceinline__ uint32_t h2(float a, float b)
{
    __half2 h = __floats2half2_rn(a, b);
    return *reinterpret_cast<uint32_t*>(&h);
}
__device__ __forceinline__ void splitw(float x0, float x1, uint32_t& hi, uint32_t& lo)
{
    __half h0 = __float2half_rn(x0);
    __half h1 = __float2half_rn(x1);
    float l0 = x0 - __half2float(h0);
    float l1 = x1 - __half2float(h1);
    __half2 hh = __halves2half2(h0, h1);
    __half2 ll = __floats2half2_rn(l0, l1);
    hi = *reinterpret_cast<uint32_t*>(&hh);
    lo = *reinterpret_cast<uint32_t*>(&ll);
}

__device__ __forceinline__ void mma_f16(float c[4],
    uint32_t a0, uint32_t a1, uint32_t a2, uint32_t a3, uint32_t b0, uint32_t b1)
{
    asm volatile(
        "mma.sync.aligned.m16n8k16.row.col.f32.f16.f16.f32 "
        "{%0,%1,%2,%3}, {%4,%5,%6,%7}, {%8,%9}, {%0,%1,%2,%3};"
        : "+f"(c[0]), "+f"(c[1]), "+f"(c[2]), "+f"(c[3])
        : "r"(a0), "r"(a1), "r"(a2), "r"(a3), "r"(b0), "r"(b1));
}

__device__ __forceinline__ uint32_t smem_u32(const void* p) {
    uint32_t a;
    asm("{ .reg .u64 t; cvta.to.shared.u64 t, %1; cvt.u32.u64 %0, t; }" : "=r"(a) : "l"(p));
    return a;
}
__device__ __forceinline__ void cpa4(uint32_t saddr, const void* g, bool v) {
    asm volatile("cp.async.ca.shared.global [%0], [%1], 4, %2;"
        :: "r"(saddr), "l"(g), "r"(v ? 4u : 0u));
}
__device__ __forceinline__ void cpa16(uint32_t saddr, const void* g) {
    asm volatile("cp.async.ca.shared.global [%0], [%1], 16;"
        :: "r"(saddr), "l"(g));
}
#define CP_COMMIT() asm volatile("cp.async.commit_group;" ::: "memory")
#define CP_WAIT1()  asm volatile("cp.async.wait_group 1;" ::: "memory")

// ---------------- weight prep (hi/lo planes) + input split (fused) ----------------
__global__ void prep_all(const float* __restrict__ conv_w, const float* __restrict__ qkv_w,
                         const float* __restrict__ fc_w, const float* __restrict__ w_in,
                         const float* __restrict__ w_out, const float* __restrict__ x)
{
    int i = blockIdx.x*256 + threadIdx.x;
    float x0, x1; uint32_t *dh, *dl;
    if (i < NC) {
        int oc = i & 127; int r = i >> 7; int ic2 = r & 63; r >>= 6;
        int tap = r % 9, d = r / 9;
        size_t base = ((size_t)(d*DIM + oc)*DIM + 2*ic2)*9 + tap;
        x0 = conv_w[base]; x1 = conv_w[base + 9]; dh = &g_cwh[i]; dl = &g_cwl[i];
    } else if (i < NC+NQ) {
        int j = i - NC; int d = j / (64*384); int l = j % (64*384);
        int k2 = l / 384, m = l % 384;
        x0 = qkv_w[((size_t)d*384 + m)*DIM + 2*k2];
        x1 = qkv_w[((size_t)d*384 + m)*DIM + 2*k2 + 1];
        dh = &g_qwh[j]; dl = &g_qwl[j];
    } else if (i < NC+NQ+NF) {
        int j = i - NC - NQ; int d = j / (64*DIM); int l = j % (64*DIM);
        int k2 = l / DIM, m = l % DIM;
        x0 = fc_w[((size_t)d*DIM + m)*DIM + 2*k2];
        x1 = fc_w[((size_t)d*DIM + m)*DIM + 2*k2 + 1];
        dh = &g_fwh[j]; dl = &g_fwl[j];
    } else if (i < NC+NQ+NF+NI) {
        int j = i - NC - NQ - NF; int k2 = j / DIM, m = j % DIM;
        x0 = w_in[(size_t)m*CIN + 2*k2]; x1 = w_in[(size_t)m*CIN + 2*k2 + 1];
        dh = &g_wih[j]; dl = &g_wil[j];
    } else if (i < NTOT) {
        int j = i - NC - NQ - NF - NI; int k2 = j / COUT, m = j % COUT;
        x0 = w_out[(size_t)m*DIM + 2*k2]; x1 = w_out[(size_t)m*DIM + 2*k2 + 1];
        dh = &g_woh[j]; dl = &g_wol[j];
    } else if (i < NTOT + NSX) {
        int j = i - NTOT;
        int p = j % HW; int r = j / HW; int k2 = r & 31; int b = r >> 5;
        float a0 = x[((size_t)b*CIN + 2*k2)*HW + p];
        float a1 = x[((size_t)b*CIN + 2*k2 + 1)*HW + p];
        g_xsp[(size_t)b*32*HW + (size_t)k2*HW + p] = h2(a0, a1);
        return;
    } else return;
    uint32_t hi, lo; splitw(x0, x1, hi, lo);
    *dh = hi; *dl = lo;
}

// ---------------- fp16x2 GEMM (2-stage cp.async, K=32 chunks, 64m x 128n, 16B loads) -----
__global__ void gemm_f16(const uint32_t* __restrict__ Wh, const uint32_t* __restrict__ Wl,
                         const uint32_t* __restrict__ Bin,
                         const float* __restrict__ bias, const float* __restrict__ res,
                         void* __restrict__ Out, int osplit, int Mtot, int K)
{
    const int b  = blockIdx.z;
    const int m0 = blockIdx.y * 64, n0 = blockIdx.x * 128;

    __shared__ uint32_t As[2][2][16][72];
    __shared__ uint32_t Bs[2][16][136];

    const int tid  = threadIdx.x;
    const int warp = tid >> 5, lane = tid & 31;
    const int wm = warp >> 2, wn = warp & 3;
    const int g = lane >> 2, t = lane & 3;
    const int arow = tid >> 4, amg = tid & 15;   // A: 16 rows x 16 m-groups of 4

    const uint32_t sA = smem_u32(As), sB = smem_u32(Bs);
    const uint32_t* Bsp = Bin + (size_t)b*(K/2)*HW;
    const int nk = K/32;
    float acc[2][4][4] = {};

#define G_ISSUE(c) do { \
        int s_ = (c) & 1; \
        cpa16(sA + (((s_*2+0)*16 + arow)*72 + amg*4)*4, \
              &Wh[(size_t)((c)*16 + arow)*Mtot + m0 + amg*4]); \
        cpa16(sA + (((s_*2+1)*16 + arow)*72 + amg*4)*4, \
              &Wl[(size_t)((c)*16 + arow)*Mtot + m0 + amg*4]); \
        _Pragma("unroll") \
        for (int j_ = 0; j_ < 2; j_++) { \
            int i_ = tid + j_*256; int tt_ = i_ >> 5; int ng_ = i_ & 31; \
            cpa16(sB + ((s_*16 + tt_)*136 + ng_*4)*4, \
                  &Bsp[(size_t)((c)*16 + tt_)*HW + n0 + ng_*4]); \
        } \
    } while(0)

    G_ISSUE(0); CP_COMMIT();
    if (nk > 1) G_ISSUE(1);
    CP_COMMIT();
    for (int c = 0; c < nk; c++) {
        const int cur = c & 1;
        CP_WAIT1();
        __syncthreads();

        #pragma unroll
        for (int sub = 0; sub < 2; sub++) {
            const int ro = sub*8;
            uint32_t ah[2][4], al[2][4];
            #pragma unroll
            for (int mt = 0; mt < 2; mt++) {
                int mrow = wm*32 + mt*16 + g;
                ah[mt][0] = As[cur][0][ro+t  ][mrow]; ah[mt][1] = As[cur][0][ro+t  ][mrow+8];
                ah[mt][2] = As[cur][0][ro+t+4][mrow]; ah[mt][3] = As[cur][0][ro+t+4][mrow+8];
                al[mt][0] = As[cur][1][ro+t  ][mrow]; al[mt][1] = As[cur][1][ro+t  ][mrow+8];
                al[mt][2] = As[cur][1][ro+t+4][mrow]; al[mt][3] = As[cur][1][ro+t+4][mrow+8];
            }
            #pragma unroll
            for (int nt = 0; nt < 4; nt++) {
                int col = wn*32 + nt*8 + g;
                uint32_t b0 = Bs[cur][ro+t][col], b1 = Bs[cur][ro+t+4][col];
                #pragma unroll
                for (int mt = 0; mt < 2; mt++) {
                    mma_f16(acc[mt][nt], ah[mt][0], ah[mt][1], ah[mt][2], ah[mt][3], b0, b1);
                    mma_f16(acc[mt][nt], al[mt][0], al[mt][1], al[mt][2], al[mt][3], b0, b1);
                }
            }
        }
        __syncthreads();
        if (c + 2 < nk) G_ISSUE(c + 2);
        CP_COMMIT();
    }
#undef G_ISSUE

    const float* Rb = res ? res + (size_t)b*Mtot*HW : nullptr;

    #pragma unroll
    for (int mt = 0; mt < 2; mt++) {
        const int row0 = m0 + wm*32 + mt*16 + g;
        const float b0v = bias ? bias[row0]     : 0.f;
        const float b1v = bias ? bias[row0 + 8] : 0.f;
        #pragma unroll
        for (int nt = 0; nt < 4; nt++) {
            int col = n0 + wn*32 + nt*8 + 2*t;
            float v00 = acc[mt][nt][0] + b0v, v01 = acc[mt][nt][1] + b0v;
            float v10 = acc[mt][nt][2] + b1v, v11 = acc[mt][nt][3] + b1v;
            if (Rb) {
                float2 r0 = *(const float2*)&Rb[(size_t)row0*HW + col];
                float2 r1 = *(const float2*)&Rb[(size_t)(row0+8)*HW + col];
                v00 += r0.x; v01 += r0.y; v10 += r1.x; v11 += r1.y;
            }
            if (!osplit) {
                float* Yb = (float*)Out + (size_t)b*Mtot*HW;
                *(float2*)&Yb[(size_t)row0*HW + col]     = make_float2(v00, v01);
                *(float2*)&Yb[(size_t)(row0+8)*HW + col] = make_float2(v10, v11);
            } else {
                float p00 = __shfl_xor_sync(0xffffffffu, v00, 4);
                float p01 = __shfl_xor_sync(0xffffffffu, v01, 4);
                float p10 = __shfl_xor_sync(0xffffffffu, v10, 4);
                float p11 = __shfl_xor_sync(0xffffffffu, v11, 4);
                if (!(g & 1)) {
                    uint32_t* Osp = (uint32_t*)Out + (size_t)b*64*HW;
                    int c2 = row0 >> 1;
                    *(uint2*)&Osp[(size_t)c2*HW + col]     = make_uint2(h2(v00,p00), h2(v01,p01));
                    *(uint2*)&Osp[(size_t)(c2+4)*HW + col] = make_uint2(h2(v10,p10), h2(v11,p11));
                }
            }
        }
    }
}

// ---------------- dilated 3x3 conv (fp16x2, 3-stage cp.async, K=32, 64m x 96n, 16B A) ----
__global__ void conv3x3_f16(const uint32_t* __restrict__ Bsp,
                            const uint32_t* __restrict__ CWh, const uint32_t* __restrict__ CWl,
                            const float* __restrict__ bias, float* __restrict__ Y, int d)
{
    const int m0 = blockIdx.x * 64;
    const int y  = blockIdx.y;
    const int b  = blockIdx.z;
    const uint32_t* Xb = Bsp + (size_t)b*64*HW;

    __shared__ uint32_t As[3][2][16][72];   // 27.0 KB
    __shared__ uint32_t Bs[3][16][104];     // 19.5 KB (aliased for bn staging after loop)

    const int tid  = threadIdx.x;
    const int warp = tid >> 5, lane = tid & 31;
    const int wm = warp >> 1, wn = warp & 1;
    const int g = lane >> 2, t = lane & 3;
    const int arow = tid >> 4, amg = tid & 15;   // A: 16 rows x 16 m-groups of 4

    const uint32_t sA = smem_u32(As), sB = smem_u32(Bs);

    int tidx[9], txs[9], roff[9], nv = 0;
    #pragma unroll
    for (int tap = 0; tap < 9; tap++) {
        int dy = tap/3 - 1, dx = tap%3 - 1;
        int yy = y + dy*d;
        if (yy >= 0 && yy < HH) {
            tidx[nv] = tap; txs[nv] = dx*d; roff[nv] = yy*WW; nv++;
        }
    }
    const int nchunks = nv * 4;             // K=32 per chunk

    float acc[6][4] = {};

#define C_ISSUE(cc) do { \
        int tv_ = (cc) >> 2, kc2_ = (cc) & 3; int icb_ = kc2_*16; int s_ = (cc) % 3; \
        const uint32_t* Wh_ = CWh + (size_t)tidx[tv_]*64*DIM; \
        const uint32_t* Wl_ = CWl + (size_t)tidx[tv_]*64*DIM; \
        cpa16(sA + (((s_*2+0)*16 + arow)*72 + amg*4)*4, \
              &Wh_[(size_t)(icb_ + arow)*DIM + m0 + amg*4]); \
        cpa16(sA + (((s_*2+1)*16 + arow)*72 + amg*4)*4, \
              &Wl_[(size_t)(icb_ + arow)*DIM + m0 + amg*4]); \
        const uint32_t* Xr_ = Xb + roff[tv_]; int sh_ = txs[tv_]; \
        _Pragma("unroll") \
        for (int j_ = 0; j_ < 6; j_++) { \
            int i_ = tid + j_*256; int tt_ = i_ / 96; int n_ = i_ - 96*tt_; \
            int xx_ = n_ + sh_; \
            bool v_ = (xx_ >= 0 && xx_ < WW); \
            int xc_ = v_ ? xx_ : 0; \
            cpa4(sB + ((s_*16 + tt_)*104 + n_)*4, \
                 &Xr_[(size_t)(icb_ + tt_)*HW + xc_], v_); \
        } \
    } while(0)

    C_ISSUE(0); CP_COMMIT();
    C_ISSUE(1); CP_COMMIT();
    for (int cc = 0; cc < nchunks; cc++) {
        const int cur = cc % 3;
        CP_WAIT1();
        __syncthreads();

        const int mrow = wm*16 + g;
        #pragma unroll
        for (int sub = 0; sub < 2; sub++) {
            const int ro = sub*8;
            uint32_t ah0 = As[cur][0][ro+t  ][mrow], ah1 = As[cur][0][ro+t  ][mrow+8];
            uint32_t ah2 = As[cur][0][ro+t+4][mrow], ah3 = As[cur][0][ro+t+4][mrow+8];
            uint32_t al0 = As[cur][1][ro+t  ][mrow], al1 = As[cur][1][ro+t  ][mrow+8];
            uint32_t al2 = As[cur][1][ro+t+4][mrow], al3 = As[cur][1][ro+t+4][mrow+8];
            #pragma unroll
            for (int nt = 0; nt < 6; nt++) {
                int col = wn*48 + nt*8 + g;
                uint32_t b0 = Bs[cur][ro+t][col], b1 = Bs[cur][ro+t+4][col];
                mma_f16(acc[nt], ah0, ah1, ah2, ah3, b0, b1);
                mma_f16(acc[nt], al0, al1, al2, al3, b0, b1);
            }
        }
        if (cc + 2 < nchunks) C_ISSUE(cc + 2);
        CP_COMMIT();
    }
#undef C_ISSUE

    float* Yb = Y + (size_t)b*DIM*HW + (size_t)y*WW;
    const int row0 = m0 + wm*16 + g;
    const float b0v = bias[row0], b1v = bias[row0 + 8];
    float s0 = 0.f, q0 = 0.f, s1 = 0.f, q1 = 0.f;
    #pragma unroll
    for (int nt = 0; nt < 6; nt++) {
        int col = wn*48 + nt*8 + 2*t;
        float v00 = acc[nt][0] + b0v, v01 = acc[nt][1] + b0v;
        float v10 = acc[nt][2] + b1v, v11 = acc[nt][3] + b1v;
        *(float2*)&Yb[(size_t)row0*HW + col]     = make_float2(v00, v01);
        *(float2*)&Yb[(size_t)(row0+8)*HW + col] = make_float2(v10, v11);
        s0 += v00 + v01; q0 += v00*v00 + v01*v01;
        s1 += v10 + v11; q1 += v10*v10 + v11*v11;
    }
    #pragma unroll
    for (int o = 1; o <= 2; o <<= 1) {
        s0 += __shfl_xor_sync(0xffffffffu, s0, o);
        q0 += __shfl_xor_sync(0xffffffffu, q0, o);
        s1 += __shfl_xor_sync(0xffffffffu, s1, o);
        q1 += __shfl_xor_sync(0xffffffffu, q1, o);
    }
    // bn partial staging aliased onto Bs (dead after main loop)
    float* sSQ = (float*)Bs;
    __syncthreads();
    if (t == 0) {
        int lr = wm*16 + g;
        sSQ[wn*64 + lr]        = s0;  sSQ[128 + wn*64 + lr]        = q0;
        sSQ[wn*64 + lr + 8]    = s1;  sSQ[128 + wn*64 + lr + 8]    = q1;
    }
    __syncthreads();
    if (tid < 64) {
        int idx = b*HH + y;
        g_ps[(size_t)(m0+tid)*NIDX + idx] = sSQ[tid] + sSQ[64 + tid];
        g_pq[(size_t)(m0+tid)*NIDX + idx] = sSQ[128 + tid] + sSQ[192 + tid];
    }
}

// ---------------- bn apply + relu (inline stats) ----------------
__global__ void bn_apply_relu(const float* __restrict__ X, const float* __restrict__ gam,
                              const float* __restrict__ beta, float* __restrict__ Yf,
                              uint32_t* __restrict__ Ysp)
{
    const int b = blockIdx.y;
    int i = blockIdx.x*256 + threadIdx.x;
    int c2 = i / (HW/4);
    int p  = (i - c2*(HW/4)) * 4;
    int c0 = 2*c2, c1 = 2*c2 + 1;

    __shared__ float st[4];
    __shared__ float rs[4][8];
    {
        float s0=0.f, q0=0.f, s1=0.f, q1=0.f;
        int tt = threadIdx.x;
        if (tt < NIDX) {
            s0 = g_ps[(size_t)c0*NIDX + tt]; q0 = g_pq[(size_t)c0*NIDX + tt];
            s1 = g_ps[(size_t)c1*NIDX + tt]; q1 = g_pq[(size_t)c1*NIDX + tt];
        }
        #pragma unroll
        for (int o = 16; o > 0; o >>= 1) {
            s0 += __shfl_xor_sync(0xffffffffu, s0, o);
            q0 += __shfl_xor_sync(0xffffffffu, q0, o);
            s1 += __shfl_xor_sync(0xffffffffu, s1, o);
            q1 += __shfl_xor_sync(0xffffffffu, q1, o);
        }
        int w = threadIdx.x >> 5;
        if ((threadIdx.x & 31) == 0) {
            rs[0][w] = s0; rs[1][w] = q0; rs[2][w] = s1; rs[3][w] = q1;
        }
        __syncthreads();
        if (threadIdx.x == 0) {
            float S0=0,Q0=0,S1=0,Q1=0;
            #pragma unroll
            for (int k = 0; k < 8; k++) { S0+=rs[0][k]; Q0+=rs[1][k]; S1+=rs[2][k]; Q1+=rs[3][k]; }
            const float invN = 1.f / (BATCH*HW);
            float mm0 = S0*invN, mm1 = S1*invN;
            st[0] = mm0; st[1] = rsqrtf(Q0*invN - mm0*mm0 + 1e-5f);
            st[2] = mm1; st[3] = rsqrtf(Q1*invN - mm1*mm1 + 1e-5f);
        }
        __syncthreads();
    }
    float m0 = st[0], r0 = st[1], m1 = st[2], r1 = st[3];
    float ga0 = gam[c0], be0 = beta[c0], ga1 = gam[c1], be1 = beta[c1];

    const float* Xb = X + (size_t)b*DIM*HW;
    float* Yb = Yf + (size_t)b*DIM*HW;
    uint32_t* Sb = Ysp + (size_t)b*64*HW;

    float4 a = *(const float4*)&Xb[(size_t)c0*HW + p];
    float4 c = *(const float4*)&Xb[(size_t)c1*HW + p];
    float y0x = fmaxf((a.x-m0)*r0*ga0+be0, 0.f), y0y = fmaxf((a.y-m0)*r0*ga0+be0, 0.f);
    float y0z = fmaxf((a.z-m0)*r0*ga0+be0, 0.f), y0w = fmaxf((a.w-m0)*r0*ga0+be0, 0.f);
    float y1x = fmaxf((c.x-m1)*r1*ga1+be1, 0.f), y1y = fmaxf((c.y-m1)*r1*ga1+be1, 0.f);
    float y1z = fmaxf((c.z-m1)*r1*ga1+be1, 0.f), y1w = fmaxf((c.w-m1)*r1*ga1+be1, 0.f);

    *(float4*)&Yb[(size_t)c0*HW + p] = make_float4(y0x, y0y, y0z, y0w);
    *(float4*)&Yb[(size_t)c1*HW + p] = make_float4(y1x, y1y, y1z, y1w);

    *(uint4*)&Sb[(size_t)c2*HW + p] =
        make_uint4(h2(y0x, y1x), h2(y0y, y1y), h2(y0z, y1z), h2(y0w, y1w));
}

// ---------------- local channel self-attention (half2 epilogue) ----------------
__global__ void attn_core(const float* __restrict__ QKV, uint32_t* __restrict__ OUT)
{
    const int b = blockIdx.z, h = blockIdx.y;
    const int p0 = blockIdx.x * 32;
    const int y  = p0 / WW, x0 = p0 % WW;
    const float* Qb = QKV + ((size_t)b*3*DIM + h*CH)*HW;
    const float* Kb = Qb + (size_t)DIM*HW;
    const float* Vb = Qb + (size_t)2*DIM*HW;

    __shared__ float qs[CH][3][34];
    __shared__ float ks[CH][3][34];
    __shared__ float vs[CH][3][34];
    __shared__ float sato[CH][33];

    const int tid = threadIdx.y*32 + threadIdx.x;
    for (int i = tid; i < CH*3*34; i += 512) {
        int xi = i % 34; int rr = i / 34; int yi = rr % 3; int c = rr / 3;
        int yy = y + yi - 1, xx = x0 + xi - 1;
        bool ok = (yy >= 0 && yy < HH && xx >= 0 && xx < WW);
        int o = c*HW + yy*WW + xx;
        qs[c][yi][xi] = ok ? Qb[o] : 0.f;
        ks[c][yi][xi] = ok ? Kb[o] : 0.f;
        vs[c][yi][xi] = ok ? Vb[o] : 0.f;
    }
    __syncthreads();

    const int nn = threadIdx.y, lx = threadIdx.x;
    float qr[9];
    #pragma unroll
    for (int t = 0; t < 9; t++) qr[t] = qs[nn][t/3][lx + t%3] * 0.25f;

    float dots[CH], vsum[CH];
    #pragma unroll
    for (int m = 0; m < CH; m++) {
        float dv = 0.f, sv = 0.f;
        #pragma unroll
        for (int t = 0; t < 9; t++) {
            dv += qr[t] * ks[m][t/3][lx + t%3];
            sv += vs[m][t/3][lx + t%3];
        }
        dots[m] = dv; vsum[m] = sv;
    }
    float mx = dots[0];
    #pragma unroll
    for (int m = 1; m < CH; m++) mx = fmaxf(mx, dots[m]);
    float s = 0.f;
    #pragma unroll
    for (int m = 0; m < CH; m++) { dots[m] = __expf(dots[m]-mx); s += dots[m]; }
    float o = 0.f;
    #pragma unroll
    for (int m = 0; m < CH; m++) o += dots[m]*vsum[m];
    sato[nn][lx] = o / s;
    __syncthreads();

    if (nn < 8) {
        float v0 = sato[2*nn][lx], v1 = sato[2*nn+1][lx];
        OUT[(size_t)b*64*HW + (size_t)(h*8 + nn)*HW + p0 + lx] = h2(v0, v1);
    }
}

// ---------------- host orchestration ----------------
extern "C" void kernel_launch(void* const* d_in, const int* in_sizes, int n_in,
                              void* d_out, int out_size)
{
    const float* x      = (const float*)d_in[0];
    const float* w_in   = (const float*)d_in[1];
    const float* b_in   = (const float*)d_in[2];
    const float* conv_w = (const float*)d_in[3];
    const float* conv_b = (const float*)d_in[4];
    const float* bn_g   = (const float*)d_in[5];
    const float* bn_b   = (const float*)d_in[6];
    const float* qkv_w  = (const float*)d_in[7];
    const float* fc_w   = (const float*)d_in[8];
    const float* fc_b   = (const float*)d_in[9];
    const float* w_out  = (const float*)d_in[10];
    const float* b_out  = (const float*)d_in[11];
    float* out = (float*)d_out;

    float *p_t, *p_bn, *p_qkv;
    uint32_t *p_hsp, *p_qsp, *p_asp, *p_xsp;
    uint32_t *p_cwh, *p_cwl, *p_qwh, *p_qwl, *p_fwh, *p_fwl, *p_wih, *p_wil, *p_woh, *p_wol;
    cudaGetSymbolAddress((void**)&p_t,   g_t);
    cudaGetSymbolAddress((void**)&p_bn,  g_bn);
    cudaGetSymbolAddress((void**)&p_qkv, g_qkv);
    cudaGetSymbolAddress((void**)&p_hsp, g_hsp);
    cudaGetSymbolAddress((void**)&p_qsp, g_qsp);
    cudaGetSymbolAddress((void**)&p_asp, g_asp);
    cudaGetSymbolAddress((void**)&p_xsp, g_xsp);
    cudaGetSymbolAddress((void**)&p_cwh, g_cwh);
    cudaGetSymbolAddress((void**)&p_cwl, g_cwl);
    cudaGetSymbolAddress((void**)&p_qwh, g_qwh);
    cudaGetSymbolAddress((void**)&p_qwl, g_qwl);
    cudaGetSymbolAddress((void**)&p_fwh, g_fwh);
    cudaGetSymbolAddress((void**)&p_fwl, g_fwl);
    cudaGetSymbolAddress((void**)&p_wih, g_wih);
    cudaGetSymbolAddress((void**)&p_wil, g_wil);
    cudaGetSymbolAddress((void**)&p_woh, g_woh);
    cudaGetSymbolAddress((void**)&p_wol, g_wol);

    prep_all<<<(NTOT + NSX + 255)/256, 256>>>(conv_w, qkv_w, fc_w, w_in, w_out, x);

    // input projection 64 -> 128, half2 output into g_hsp
    {
        dim3 g(HW/128, DIM/64, BATCH);
        gemm_f16<<<g, 256>>>(p_wih, p_wil, p_xsp, b_in, nullptr, p_hsp, 1, DIM, CIN);
    }

    for (int i = 0; i < DEPTH; i++) {
        const int d = 1 << i;
        {   // dilated conv (K=32 chunks, 3-stage, 256 threads)
            dim3 g(2, HH, BATCH);
            conv3x3_f16<<<g, 256>>>(p_hsp, p_cwh + (size_t)i*9*64*DIM,
                                    p_cwl + (size_t)i*9*64*DIM, conv_b + i*DIM, p_t, d);
        }
        {   // bn + relu -> fp32 residual + half2 qkv input
            dim3 g((64*HW/4)/256, BATCH);
            bn_apply_relu<<<g, 256>>>(p_t, bn_g + i*DIM, bn_b + i*DIM, p_bn, p_qsp);
        }
        {   // qkv: 128 -> 384
            dim3 g(HW/128, (3*DIM)/64, BATCH);
            gemm_f16<<<g, 256>>>(p_qwh + (size_t)i*64*3*DIM, p_qwl + (size_t)i*64*3*DIM,
                                 p_qsp, nullptr, nullptr, p_qkv, 0, 3*DIM, DIM);
        }
        {   // attention -> half2 att
            dim3 g(HW/32, HEADS, BATCH);
            dim3 blk(32, CH);
            attn_core<<<g, blk>>>(p_qkv, p_asp);
        }
        {   // fc + bias + residual -> half2 h
            dim3 g(HW/128, DIM/64, BATCH);
            gemm_f16<<<g, 256>>>(p_fwh + (size_t)i*64*DIM, p_fwl + (size_t)i*64*DIM,
                                 p_asp, fc_b + i*DIM, p_bn, p_hsp, 1, DIM, DIM);
        }
    }

    // output projection 128 -> 64
    {
        dim3 g(HW/128, COUT/64, BATCH);
        gemm_f16<<<g, 256>>>(p_woh, p_wol, p_hsp, b_out, nullptr, out, 0, COUT, DIM);
    }
}